// round 8
// baseline (speedup 1.0000x reference)
#include <cuda_runtime.h>

// ---------------------------------------------------------------------------
// QConv2d: out = (uc2 (x) ux (x) uy) . rho . (uc2 (x) ux (x) uy)^T
//   row index r = f*64 + i*8 + j : ux acts on digit i, uy acts on digit j.
// Two 8x8-block passes on a padded 128x136 smem tile:
//   Pass A (fused gmem load): per (j,j') block, O = uy . X . uy^T
//   Pass B:                   per (i,i') block, O = ux . X . ux^T
// then fused uc2 . M . uc2^T epilogue streamed to gmem.
// Stage 1 of each pass uses packed f32x2 FMA (x-pairs from 128-bit loads;
// uy/ux scalars pre-duplicated into smem as u64, broadcast ld.shared.b64).
// ---------------------------------------------------------------------------

#define PSTR 136
#define SM_UYD 17408   // u64 uy_dup[64]  (128 floats)
#define SM_UXD 17536   // u64 ux_dup[64]  (128 floats)
#define SM_UYS 17664   // float uy[64]
#define SM_UXS 17728   // float ux[64]
#define SM_UC  17792   // float uc2[8]
#define SMEM_BYTES (17800 * 4)   // 71200 B -> 2 CTAs/SM

typedef unsigned long long u64t;

__device__ __forceinline__ u64t pk2(float lo, float hi) {
    u64t r; asm("mov.b64 %0, {%1,%2};" : "=l"(r) : "f"(lo), "f"(hi)); return r;
}
__device__ __forceinline__ u64t fma2(u64t a, u64t b, u64t c) {
    u64t d; asm("fma.rn.f32x2 %0, %1, %2, %3;" : "=l"(d) : "l"(a), "l"(b), "l"(c));
    return d;
}
__device__ __forceinline__ u64t mul2(u64t a, u64t b) {
    u64t d; asm("mul.rn.f32x2 %0, %1, %2;" : "=l"(d) : "l"(a), "l"(b));
    return d;
}
__device__ __forceinline__ void upk2(u64t v, float& lo, float& hi) {
    asm("mov.b64 {%0,%1}, %2;" : "=f"(lo), "=f"(hi) : "l"(v));
}
__device__ __forceinline__ u64t lds64(const u64t* p) {
    u64t r; asm("ld.shared.b64 %0, [%1];" : "=l"(r) : "l"((size_t)__cvta_generic_to_shared(p)));
    return r;
}

__global__ void __launch_bounds__(256, 2)
qconv_kernel(const float* __restrict__ rho,
             const float* __restrict__ ux,
             const float* __restrict__ uy,
             const float* __restrict__ uc,
             float* __restrict__ out)
{
    extern __shared__ float s[];
    float* buf = s;
    const int b = blockIdx.x;
    const int t = threadIdx.x;

    // stage weights: scalars + duplicated u64 copies
    if (t < 64) {
        float vy = uy[t], vx = ux[t];
        s[SM_UYS + t] = vy;  s[SM_UXS + t] = vx;
        ((u64t*)(s + SM_UYD))[t] = pk2(vy, vy);
        ((u64t*)(s + SM_UXD))[t] = pk2(vx, vx);
    } else if (t < 72) {
        int q = t - 64;
        s[SM_UC + q] = uc[(q >> 1) * 4 + 2 + (q & 1)];
    }
    __syncthreads();

    // ====================== Pass A: (j,j') blocks, uy both sides ===========
    // thread block: rows rb*8+a (global), cols cb*8 .. cb*8+7
    {
        const int rb = t >> 4, cb = t & 15;
        const float* src = rho + (size_t)b * 16384 + (size_t)rb * 8 * 128 + cb * 8;
        const u64t* uyd = (const u64t*)(s + SM_UYD);

        // stage 1: Yp[a][jp] = sum_j uy[a][j] * X[j][jp-pair]   (fused load)
        u64t Yp[8][4];
        {
            float4 q0 = *(const float4*)(src);
            float4 q1 = *(const float4*)(src + 4);
            u64t xp[4] = { pk2(q0.x,q0.y), pk2(q0.z,q0.w), pk2(q1.x,q1.y), pk2(q1.z,q1.w) };
            #pragma unroll
            for (int a = 0; a < 8; ++a) {
                u64t u = lds64(uyd + a * 8);
                #pragma unroll
                for (int jp = 0; jp < 4; ++jp) Yp[a][jp] = mul2(u, xp[jp]);
            }
        }
        #pragma unroll
        for (int j = 1; j < 8; ++j) {
            float4 q0 = *(const float4*)(src + j * 128);
            float4 q1 = *(const float4*)(src + j * 128 + 4);
            u64t xp[4] = { pk2(q0.x,q0.y), pk2(q0.z,q0.w), pk2(q1.x,q1.y), pk2(q1.z,q1.w) };
            #pragma unroll
            for (int a = 0; a < 8; ++a) {
                u64t u = lds64(uyd + a * 8 + j);
                #pragma unroll
                for (int jp = 0; jp < 4; ++jp) Yp[a][jp] = fma2(u, xp[jp], Yp[a][jp]);
            }
        }
        // unpack Y to scalars
        float Ys[8][8];
        #pragma unroll
        for (int a = 0; a < 8; ++a)
            #pragma unroll
            for (int jp = 0; jp < 4; ++jp)
                upk2(Yp[a][jp], Ys[a][2*jp], Ys[a][2*jp+1]);

        // stage 2: O[a][b] = sum_j' Ys[a][j'] * uy[b][j'], b in two halves
        const float* uys = s + SM_UYS;
        float* dst = buf + (rb * 8) * PSTR + cb * 8;
        #pragma unroll
        for (int h = 0; h < 2; ++h) {
            float Oc[8][4];
            #pragma unroll
            for (int b4 = 0; b4 < 4; ++b4) {
                float sc = uys[(h * 4 + b4) * 8];
                #pragma unroll
                for (int a = 0; a < 8; ++a) Oc[a][b4] = Ys[a][0] * sc;
            }
            #pragma unroll
            for (int jq = 1; jq < 8; ++jq) {
                #pragma unroll
                for (int b4 = 0; b4 < 4; ++b4) {
                    float sc = uys[(h * 4 + b4) * 8 + jq];
                    #pragma unroll
                    for (int a = 0; a < 8; ++a)
                        Oc[a][b4] = fmaf(Ys[a][jq], sc, Oc[a][b4]);
                }
            }
            #pragma unroll
            for (int a = 0; a < 8; ++a)
                *(float4*)(dst + a * PSTR + h * 4) =
                    make_float4(Oc[a][0], Oc[a][1], Oc[a][2], Oc[a][3]);
        }
    }
    __syncthreads();

    // ====================== Pass B: (i,i') blocks, ux both sides ===========
    {
        const int rb2 = t >> 4, cb2 = t & 15;
        const int f  = rb2 >> 3, j  = rb2 & 7;
        const int fp = cb2 >> 3, jp_ = cb2 & 7;
        float* base = buf + (f * 64 + j) * PSTR + fp * 64 + jp_;
        const u64t* uxd = (const u64t*)(s + SM_UXD);

        // stage 1: Zp[a][ip] = sum_i ux[a][i] * X[i][ip-pair]
        u64t Zp[8][4];
        {
            float x[8];
            #pragma unroll
            for (int ii = 0; ii < 8; ++ii) x[ii] = base[ii * 8];
            u64t xp[4] = { pk2(x[0],x[1]), pk2(x[2],x[3]), pk2(x[4],x[5]), pk2(x[6],x[7]) };
            #pragma unroll
            for (int a = 0; a < 8; ++a) {
                u64t u = lds64(uxd + a * 8);
                #pragma unroll
                for (int ip = 0; ip < 4; ++ip) Zp[a][ip] = mul2(u, xp[ip]);
            }
        }
        #pragma unroll
        for (int i = 1; i < 8; ++i) {
            float x[8];
            #pragma unroll
            for (int ii = 0; ii < 8; ++ii) x[ii] = base[i * 8 * PSTR + ii * 8];
            u64t xp[4] = { pk2(x[0],x[1]), pk2(x[2],x[3]), pk2(x[4],x[5]), pk2(x[6],x[7]) };
            #pragma unroll
            for (int a = 0; a < 8; ++a) {
                u64t u = lds64(uxd + a * 8 + i);
                #pragma unroll
                for (int ip = 0; ip < 4; ++ip) Zp[a][ip] = fma2(u, xp[ip], Zp[a][ip]);
            }
        }
        float Zs[8][8];
        #pragma unroll
        for (int a = 0; a < 8; ++a)
            #pragma unroll
            for (int ip = 0; ip < 4; ++ip)
                upk2(Zp[a][ip], Zs[a][2*ip], Zs[a][2*ip+1]);

        // stage 2: O[a][bb] = sum_i' Zs[a][i'] * ux[bb][i'], scalar stores stride 8
        const float* uxs = s + SM_UXS;
        #pragma unroll
        for (int h = 0; h < 2; ++h) {
            float Oc[8][4];
            #pragma unroll
            for (int b4 = 0; b4 < 4; ++b4) {
                float sc = uxs[(h * 4 + b4) * 8];
                #pragma unroll
                for (int a = 0; a < 8; ++a) Oc[a][b4] = Zs[a][0] * sc;
            }
            #pragma unroll
            for (int iq = 1; iq < 8; ++iq) {
                #pragma unroll
                for (int b4 = 0; b4 < 4; ++b4) {
                    float sc = uxs[(h * 4 + b4) * 8 + iq];
                    #pragma unroll
                    for (int a = 0; a < 8; ++a)
                        Oc[a][b4] = fmaf(Zs[a][iq], sc, Oc[a][b4]);
                }
            }
            #pragma unroll
            for (int a = 0; a < 8; ++a)
                #pragma unroll
                for (int b4 = 0; b4 < 4; ++b4)
                    base[a * 8 * PSTR + (h * 4 + b4) * 8] = Oc[a][b4];
        }
    }
    __syncthreads();

    // ===== epilogue: out[gv, g'v'] = sum_{f,f'} c[g,f] c[g',f'] M[fv, f'v'] ==
    {
        const int wid = t >> 5, lane = t & 31;
        const int vp0 = (lane & 15) * 4;
        float* outb = out + (size_t)b * 65536;
        float cg0[4], cg1[4];
        #pragma unroll
        for (int g = 0; g < 4; ++g) {
            cg0[g] = s[SM_UC + g * 2];
            cg1[g] = s[SM_UC + g * 2 + 1];
        }

        #pragma unroll 1
        for (int rr = 0; rr < 32; ++rr) {
            const int p = wid * 32 + rr;       // output row 0..255
            const int g = p >> 6, v = p & 63;
            const float a0 = cg0[g], a1 = cg1[g];
            const float* row0 = buf + v * PSTR;          // f = 0
            const float* row1 = buf + (64 + v) * PSTR;   // f = 1
            float4 m00 = *(const float4*)(row0 + vp0);        // f'=0
            float4 m01 = *(const float4*)(row0 + 64 + vp0);   // f'=1
            float4 m10 = *(const float4*)(row1 + vp0);
            float4 m11 = *(const float4*)(row1 + 64 + vp0);
            float4 t0, t1;
            t0.x = fmaf(a1, m10.x, a0 * m00.x);
            t0.y = fmaf(a1, m10.y, a0 * m00.y);
            t0.z = fmaf(a1, m10.z, a0 * m00.z);
            t0.w = fmaf(a1, m10.w, a0 * m00.w);
            t1.x = fmaf(a1, m11.x, a0 * m01.x);
            t1.y = fmaf(a1, m11.y, a0 * m01.y);
            t1.z = fmaf(a1, m11.z, a0 * m01.z);
            t1.w = fmaf(a1, m11.w, a0 * m01.w);
            #pragma unroll
            for (int it = 0; it < 2; ++it) {
                const int gp = (it << 1) | (lane >> 4);
                const float p0 = cg0[gp], p1 = cg1[gp];
                float4 o;
                o.x = fmaf(p1, t1.x, p0 * t0.x);
                o.y = fmaf(p1, t1.y, p0 * t0.y);
                o.z = fmaf(p1, t1.z, p0 * t0.z);
                o.w = fmaf(p1, t1.w, p0 * t0.w);
                *(float4*)(outb + p * 256 + gp * 64 + vp0) = o;
            }
        }
    }
}

extern "C" void kernel_launch(void* const* d_in, const int* in_sizes, int n_in,
                              void* d_out, int out_size) {
    const float* rho = (const float*)d_in[0];
    const float* ux  = (const float*)d_in[1];
    const float* uy  = (const float*)d_in[2];
    const float* uc  = (const float*)d_in[3];
    float* out = (float*)d_out;

    const int B = in_sizes[0] >> 14;   // elements / (128*128)

    cudaFuncSetAttribute(qconv_kernel,
                         cudaFuncAttributeMaxDynamicSharedMemorySize, SMEM_BYTES);
    qconv_kernel<<<B, 256, SMEM_BYTES>>>(rho, ux, uy, uc, out);
}

// round 9
// speedup vs baseline: 1.0845x; 1.0845x over previous
#include <cuda_runtime.h>

// ---------------------------------------------------------------------------
// QConv2d: out = (uc2 (x) ux (x) uy) . rho . (uc2 (x) ux (x) uy)^T
//   row index r = f*64 + i*8 + j : ux acts on digit i, uy acts on digit j.
// Two 8x8-block passes on a padded 128x136 smem tile:
//   Pass A (fused gmem load): per (j,j') block, O = uy . X . uy^T
//   Pass B:                   per (i,i') block, O = ux . X . ux^T
// then a v-major uc2 . M . uc2^T epilogue (each M block loaded once, all four
// g-rows produced from registers, packed f32x2 FMA with pre-duplicated
// coefficients -> zero runtime packing).
// ---------------------------------------------------------------------------

#define PSTR 136
#define SM_UYD 17408   // u64 uy_dup[64]  (128 floats)
#define SM_UXD 17536   // u64 ux_dup[64]  (128 floats)
#define SM_UYS 17664   // float uy[64]
#define SM_UXS 17728   // float ux[64]
#define SM_UC  17792   // float uc2[8]
#define SMEM_BYTES (17800 * 4)   // 71200 B -> 2 CTAs/SM

typedef unsigned long long u64t;

__device__ __forceinline__ u64t pk2(float lo, float hi) {
    u64t r; asm("mov.b64 %0, {%1,%2};" : "=l"(r) : "f"(lo), "f"(hi)); return r;
}
__device__ __forceinline__ u64t fma2(u64t a, u64t b, u64t c) {
    u64t d; asm("fma.rn.f32x2 %0, %1, %2, %3;" : "=l"(d) : "l"(a), "l"(b), "l"(c));
    return d;
}
__device__ __forceinline__ u64t mul2(u64t a, u64t b) {
    u64t d; asm("mul.rn.f32x2 %0, %1, %2;" : "=l"(d) : "l"(a), "l"(b));
    return d;
}
__device__ __forceinline__ void upk2(u64t v, float& lo, float& hi) {
    asm("mov.b64 {%0,%1}, %2;" : "=f"(lo), "=f"(hi) : "l"(v));
}
__device__ __forceinline__ u64t lds64(const u64t* p) {
    u64t r; asm("ld.shared.b64 %0, [%1];" : "=l"(r) : "l"((size_t)__cvta_generic_to_shared(p)));
    return r;
}

__global__ void __launch_bounds__(256, 2)
qconv_kernel(const float* __restrict__ rho,
             const float* __restrict__ ux,
             const float* __restrict__ uy,
             const float* __restrict__ uc,
             float* __restrict__ out)
{
    extern __shared__ float s[];
    float* buf = s;
    const int b = blockIdx.x;
    const int t = threadIdx.x;

    // stage weights: scalars + duplicated u64 copies
    if (t < 64) {
        float vy = uy[t], vx = ux[t];
        s[SM_UYS + t] = vy;  s[SM_UXS + t] = vx;
        ((u64t*)(s + SM_UYD))[t] = pk2(vy, vy);
        ((u64t*)(s + SM_UXD))[t] = pk2(vx, vx);
    } else if (t < 72) {
        int q = t - 64;
        s[SM_UC + q] = uc[(q >> 1) * 4 + 2 + (q & 1)];
    }
    __syncthreads();

    // ====================== Pass A: (j,j') blocks, uy both sides ===========
    {
        const int rb = t >> 4, cb = t & 15;
        const float* src = rho + (size_t)b * 16384 + (size_t)rb * 8 * 128 + cb * 8;
        const u64t* uyd = (const u64t*)(s + SM_UYD);

        // stage 1: Yp[a][jp] = sum_j uy[a][j] * X[j][jp-pair]   (fused load)
        u64t Yp[8][4];
        {
            float4 q0 = *(const float4*)(src);
            float4 q1 = *(const float4*)(src + 4);
            u64t xp[4] = { pk2(q0.x,q0.y), pk2(q0.z,q0.w), pk2(q1.x,q1.y), pk2(q1.z,q1.w) };
            #pragma unroll
            for (int a = 0; a < 8; ++a) {
                u64t u = lds64(uyd + a * 8);
                #pragma unroll
                for (int jp = 0; jp < 4; ++jp) Yp[a][jp] = mul2(u, xp[jp]);
            }
        }
        #pragma unroll
        for (int j = 1; j < 8; ++j) {
            float4 q0 = *(const float4*)(src + j * 128);
            float4 q1 = *(const float4*)(src + j * 128 + 4);
            u64t xp[4] = { pk2(q0.x,q0.y), pk2(q0.z,q0.w), pk2(q1.x,q1.y), pk2(q1.z,q1.w) };
            #pragma unroll
            for (int a = 0; a < 8; ++a) {
                u64t u = lds64(uyd + a * 8 + j);
                #pragma unroll
                for (int jp = 0; jp < 4; ++jp) Yp[a][jp] = fma2(u, xp[jp], Yp[a][jp]);
            }
        }
        float Ys[8][8];
        #pragma unroll
        for (int a = 0; a < 8; ++a)
            #pragma unroll
            for (int jp = 0; jp < 4; ++jp)
                upk2(Yp[a][jp], Ys[a][2*jp], Ys[a][2*jp+1]);

        // stage 2: O[a][b] = sum_j' Ys[a][j'] * uy[b][j']
        const float* uys = s + SM_UYS;
        float* dst = buf + (rb * 8) * PSTR + cb * 8;
        #pragma unroll
        for (int h = 0; h < 2; ++h) {
            float Oc[8][4];
            #pragma unroll
            for (int b4 = 0; b4 < 4; ++b4) {
                float sc = uys[(h * 4 + b4) * 8];
                #pragma unroll
                for (int a = 0; a < 8; ++a) Oc[a][b4] = Ys[a][0] * sc;
            }
            #pragma unroll
            for (int jq = 1; jq < 8; ++jq) {
                #pragma unroll
                for (int b4 = 0; b4 < 4; ++b4) {
                    float sc = uys[(h * 4 + b4) * 8 + jq];
                    #pragma unroll
                    for (int a = 0; a < 8; ++a)
                        Oc[a][b4] = fmaf(Ys[a][jq], sc, Oc[a][b4]);
                }
            }
            #pragma unroll
            for (int a = 0; a < 8; ++a)
                *(float4*)(dst + a * PSTR + h * 4) =
                    make_float4(Oc[a][0], Oc[a][1], Oc[a][2], Oc[a][3]);
        }
    }
    __syncthreads();

    // ====================== Pass B: (i,i') blocks, ux both sides ===========
    {
        const int rb2 = t >> 4, cb2 = t & 15;
        const int f  = rb2 >> 3, j  = rb2 & 7;
        const int fp = cb2 >> 3, jp_ = cb2 & 7;
        float* base = buf + (f * 64 + j) * PSTR + fp * 64 + jp_;
        const u64t* uxd = (const u64t*)(s + SM_UXD);

        u64t Zp[8][4];
        {
            float x[8];
            #pragma unroll
            for (int ii = 0; ii < 8; ++ii) x[ii] = base[ii * 8];
            u64t xp[4] = { pk2(x[0],x[1]), pk2(x[2],x[3]), pk2(x[4],x[5]), pk2(x[6],x[7]) };
            #pragma unroll
            for (int a = 0; a < 8; ++a) {
                u64t u = lds64(uxd + a * 8);
                #pragma unroll
                for (int ip = 0; ip < 4; ++ip) Zp[a][ip] = mul2(u, xp[ip]);
            }
        }
        #pragma unroll
        for (int i = 1; i < 8; ++i) {
            float x[8];
            #pragma unroll
            for (int ii = 0; ii < 8; ++ii) x[ii] = base[i * 8 * PSTR + ii * 8];
            u64t xp[4] = { pk2(x[0],x[1]), pk2(x[2],x[3]), pk2(x[4],x[5]), pk2(x[6],x[7]) };
            #pragma unroll
            for (int a = 0; a < 8; ++a) {
                u64t u = lds64(uxd + a * 8 + i);
                #pragma unroll
                for (int ip = 0; ip < 4; ++ip) Zp[a][ip] = fma2(u, xp[ip], Zp[a][ip]);
            }
        }
        float Zs[8][8];
        #pragma unroll
        for (int a = 0; a < 8; ++a)
            #pragma unroll
            for (int ip = 0; ip < 4; ++ip)
                upk2(Zp[a][ip], Zs[a][2*ip], Zs[a][2*ip+1]);

        const float* uxs = s + SM_UXS;
        #pragma unroll
        for (int h = 0; h < 2; ++h) {
            float Oc[8][4];
            #pragma unroll
            for (int b4 = 0; b4 < 4; ++b4) {
                float sc = uxs[(h * 4 + b4) * 8];
                #pragma unroll
                for (int a = 0; a < 8; ++a) Oc[a][b4] = Zs[a][0] * sc;
            }
            #pragma unroll
            for (int iq = 1; iq < 8; ++iq) {
                #pragma unroll
                for (int b4 = 0; b4 < 4; ++b4) {
                    float sc = uxs[(h * 4 + b4) * 8 + iq];
                    #pragma unroll
                    for (int a = 0; a < 8; ++a)
                        Oc[a][b4] = fmaf(Zs[a][iq], sc, Oc[a][b4]);
                }
            }
            #pragma unroll
            for (int a = 0; a < 8; ++a)
                #pragma unroll
                for (int b4 = 0; b4 < 4; ++b4)
                    base[a * 8 * PSTR + (h * 4 + b4) * 8] = Oc[a][b4];
        }
    }
    __syncthreads();

    // ===== v-major epilogue: load each M block once, emit all 4 g rows ======
    // out[(g*64+v)][g'*64+v'] = sum_{f,f'} c[g,f] c[g',f'] M[f*64+v][f'*64+v']
    {
        const int wid = t >> 5, lane = t & 31;
        const int vp0 = (lane & 15) * 4;
        const int hi  = lane >> 4;               // selects g' = 2*it + hi
        float* outb = out + (size_t)b * 65536;

        u64t c0d[4], c1d[4];                     // dup'd uc2 coefficients
        #pragma unroll
        for (int g = 0; g < 4; ++g) {
            float a0 = s[SM_UC + g * 2], a1 = s[SM_UC + g * 2 + 1];
            c0d[g] = pk2(a0, a0);
            c1d[g] = pk2(a1, a1);
        }

        #pragma unroll 2
        for (int rr = 0; rr < 8; ++rr) {
            const int v = wid * 8 + rr;          // 0..63
            const float* row0 = buf + v * PSTR;          // f = 0
            const float* row1 = buf + (64 + v) * PSTR;   // f = 1
            float4 q00 = *(const float4*)(row0 + vp0);        // f'=0
            float4 q01 = *(const float4*)(row0 + 64 + vp0);   // f'=1
            float4 q10 = *(const float4*)(row1 + vp0);
            float4 q11 = *(const float4*)(row1 + 64 + vp0);
            u64t m00a = ((u64t*)&q00)[0], m00b = ((u64t*)&q00)[1];
            u64t m01a = ((u64t*)&q01)[0], m01b = ((u64t*)&q01)[1];
            u64t m10a = ((u64t*)&q10)[0], m10b = ((u64t*)&q10)[1];
            u64t m11a = ((u64t*)&q11)[0], m11b = ((u64t*)&q11)[1];

            #pragma unroll
            for (int g = 0; g < 4; ++g) {
                u64t t0a = fma2(c1d[g], m10a, mul2(c0d[g], m00a));
                u64t t0b = fma2(c1d[g], m10b, mul2(c0d[g], m00b));
                u64t t1a = fma2(c1d[g], m11a, mul2(c0d[g], m01a));
                u64t t1b = fma2(c1d[g], m11b, mul2(c0d[g], m01b));
                float* orow = outb + (g * 64 + v) * 256;
                #pragma unroll
                for (int it = 0; it < 2; ++it) {
                    const int gp = (it << 1) | hi;
                    u64t oa = fma2(c1d[gp], t1a, mul2(c0d[gp], t0a));
                    u64t ob = fma2(c1d[gp], t1b, mul2(c0d[gp], t0b));
                    float4 o;
                    ((u64t*)&o)[0] = oa;
                    ((u64t*)&o)[1] = ob;
                    *(float4*)(orow + gp * 64 + vp0) = o;
                }
            }
        }
    }
}

extern "C" void kernel_launch(void* const* d_in, const int* in_sizes, int n_in,
                              void* d_out, int out_size) {
    const float* rho = (const float*)d_in[0];
    const float* ux  = (const float*)d_in[1];
    const float* uy  = (const float*)d_in[2];
    const float* uc  = (const float*)d_in[3];
    float* out = (float*)d_out;

    const int B = in_sizes[0] >> 14;   // elements / (128*128)

    cudaFuncSetAttribute(qconv_kernel,
                         cudaFuncAttributeMaxDynamicSharedMemorySize, SMEM_BYTES);
    qconv_kernel<<<B, 256, SMEM_BYTES>>>(rho, ux, uy, uc, out);
}